// round 9
// baseline (speedup 1.0000x reference)
#include <cuda_runtime.h>
#include <cstdint>

// Correlation layer: out[b, (dy+4)*9+(dx+4), y, x] =
//   (1/C) * sum_c first[b,c,y,x] * second[b,c,y+dy,x+dx]   (zero-padded)
// B=8, C=256, H=96, W=160, MAX_DISP=4 -> 81 displacements.
//
// R8 = R7 tiling + mov-free FFMA2 on even displacements:
//   FFMA2 operands are natural aligned halves of LDS.128 float4 loads,
//   so the packs fold to register aliasing (no MOVs refilling the fma pipe).

#define MAXD    4
#define NDISP   9
#define BATCH   8
#define CHN     256
#define HH      96
#define WW      160
#define HW      (HH*WW)

#define TY      4
#define TX      32
#define PX      8              // pixels per thread (x-strip)
#define CH      8
#define NITER   (CHN/CH)       // 32

#define BROWS   (TY + 2*MAXD)  // 12
#define BCOLS   40             // data cols in B halo row
#define BSTR    44             // padded B row stride (floats)
#define ASTR    36             // padded A row stride (floats)
#define BTILEP  (BROWS*BSTR)   // 528 per channel
#define ATILEP  (TY*ASTR)      // 144 per channel
#define BUF_FLOATS (CH*(BTILEP+ATILEP))   // 5376 floats (21504 B)

#define NTHREADS 144           // 4 xg * 4 yy * 9 w

#define NB4     (CH*BROWS*(BCOLS/4))   // 960
#define NA4     (CH*TY*(TX/4))         // 256
#define NTOT4   (NB4+NA4)              // 1216
#define NSLOT   9                      // ceil(1216/144)

__device__ __forceinline__ uint32_t smem_u32(const void* p) {
    return (uint32_t)__cvta_generic_to_shared(p);
}
__device__ __forceinline__ void cp16(uint32_t s, const void* g, int srcsz) {
    asm volatile("cp.async.cg.shared.global [%0], [%1], 16, %2;\n"
                 :: "r"(s), "l"(g), "r"(srcsz));
}
__device__ __forceinline__ void cp_commit() {
    asm volatile("cp.async.commit_group;\n" ::: "memory");
}
template<int N>
__device__ __forceinline__ void cp_wait() {
    asm volatile("cp.async.wait_group %0;\n" :: "n"(N) : "memory");
}

// ---- packed f32x2 helpers ----
typedef unsigned long long u64;
__device__ __forceinline__ u64 pack2(float lo, float hi) {
    u64 r;
    asm("mov.b64 %0, {%1, %2};" : "=l"(r) : "f"(lo), "f"(hi));
    return r;
}
__device__ __forceinline__ void ffma2(u64& d, u64 a, u64 b) {
    asm("fma.rn.f32x2 %0, %1, %2, %0;" : "+l"(d) : "l"(a), "l"(b));
}
__device__ __forceinline__ void unpack2(float& lo, float& hi, u64 v) {
    asm("mov.b64 {%0, %1}, %2;" : "=f"(lo), "=f"(hi) : "l"(v));
}

__global__ __launch_bounds__(NTHREADS, 3)
void corr_kernel(const float* __restrict__ first,
                 const float* __restrict__ second,
                 float* __restrict__ out)
{
    __shared__ float smem[2 * BUF_FLOATS];   // 43008 B

    const int xt  = blockIdx.x * TX;
    const int y0  = blockIdx.y * TY;
    const int b   = blockIdx.z;
    const int tid = threadIdx.x;

    // ---- precompute staging slots ----
    const float* gsrc[NSLOT];
    int          gsz [NSLOT];
    uint32_t     sdst[NSLOT];

    const size_t base = (size_t)b * CHN * HW;
    const uint32_t smem0 = smem_u32(smem);

    #pragma unroll
    for (int k = 0; k < NSLOT; ++k) {
        const int s = tid + k * NTHREADS;
        gsz[k]  = -1;
        gsrc[k] = first;
        sdst[k] = smem0;
        if (s < NB4) {
            const int c   = s / 120;
            const int rem = s - c * 120;
            const int r   = rem / 10;
            const int q   = rem - r * 10;
            const int gy  = y0 - MAXD + r;
            const int gx  = xt - MAXD + 4 * q;
            const bool ok = ((unsigned)gy < (unsigned)HH) && (gx >= 0) && (gx + 4 <= WW);
            gsz[k]  = ok ? 16 : 0;
            gsrc[k] = ok ? (second + base + ((size_t)c * HH + gy) * WW + gx) : second;
            sdst[k] = smem0 + (uint32_t)(c * BTILEP + r * BSTR + 4 * q) * 4u;
        } else if (s < NTOT4) {
            const int j   = s - NB4;
            const int c   = j >> 5;
            const int rem = j & 31;
            const int r   = rem >> 3;
            const int q   = rem & 7;
            gsz[k]  = 16;
            gsrc[k] = first + base + ((size_t)c * HH + y0 + r) * WW + xt + 4 * q;
            sdst[k] = smem0 + (uint32_t)(CH * BTILEP + c * ATILEP + r * ASTR + 4 * q) * 4u;
        }
    }

    const int xg = tid & 3;
    const int yy = (tid >> 2) & 3;
    const int w  = tid >> 4;          // dy index 0..8

    // even j packed over pixel pairs; odd j scalar
    u64   acc2[4][5];                 // [pixel-pair][j/2]
    float acco[PX][4];                // [pixel][(j-1)/2]
    #pragma unroll
    for (int i = 0; i < 4; ++i)
        #pragma unroll
        for (int j = 0; j < 5; ++j)
            acc2[i][j] = 0ull;
    #pragma unroll
    for (int i = 0; i < PX; ++i)
        #pragma unroll
        for (int j = 0; j < 4; ++j)
            acco[i][j] = 0.0f;

    // ---- prologue: stage chunk 0 ----
    #pragma unroll
    for (int k = 0; k < NSLOT; ++k)
        if (gsz[k] >= 0) {
            cp16(sdst[k], gsrc[k], gsz[k]);
            gsrc[k] += CH * HW;
        }
    cp_commit();

    int buf = 0;
    #pragma unroll 1
    for (int it = 0; it < NITER; ++it) {
        const uint32_t nbuf_off = (uint32_t)((buf ^ 1) * BUF_FLOATS * 4);
        if (it + 1 < NITER) {
            #pragma unroll
            for (int k = 0; k < NSLOT; ++k)
                if (gsz[k] >= 0) {
                    cp16(sdst[k] + nbuf_off, gsrc[k], gsz[k]);
                    gsrc[k] += CH * HW;
                }
            cp_commit();
            cp_wait<1>();
        } else {
            cp_wait<0>();
        }
        __syncthreads();

        const float* Bb = smem + buf * BUF_FLOATS;
        const float* Ab = Bb + CH * BTILEP;
        #pragma unroll
        for (int cc = 0; cc < CH; ++cc) {
            const float* arow = &Ab[cc * ATILEP + yy * ASTR + 8 * xg];
            const float4 a0 = *reinterpret_cast<const float4*>(arow);
            const float4 a1 = *reinterpret_cast<const float4*>(arow + 4);

            // Pixel p = 8*xg+i uses halo cols 8*xg .. 8*xg+15
            const float* brow = &Bb[cc * BTILEP + (yy + w) * BSTR + 8 * xg];
            const float4 b0 = *reinterpret_cast<const float4*>(brow);
            const float4 b1 = *reinterpret_cast<const float4*>(brow + 4);
            const float4 b2 = *reinterpret_cast<const float4*>(brow + 8);
            const float4 b3 = *reinterpret_cast<const float4*>(brow + 12);

            // Natural aligned pairs straight from the float4 loads (no repacking)
            const u64 ap[4] = { pack2(a0.x, a0.y), pack2(a0.z, a0.w),
                                pack2(a1.x, a1.y), pack2(a1.z, a1.w) };
            const u64 bp[8] = { pack2(b0.x, b0.y), pack2(b0.z, b0.w),
                                pack2(b1.x, b1.y), pack2(b1.z, b1.w),
                                pack2(b2.x, b2.y), pack2(b2.z, b2.w),
                                pack2(b3.x, b3.y), pack2(b3.z, b3.w) };

            // even j = 2*jp: acc2[i2][jp] += ap[i2] * bp[i2+jp]   (20 FFMA2)
            #pragma unroll
            for (int i2 = 0; i2 < 4; ++i2)
                #pragma unroll
                for (int jp = 0; jp < 5; ++jp)
                    ffma2(acc2[i2][jp], ap[i2], bp[i2 + jp]);

            // odd j: scalar FFMA (32)
            const float a[PX]  = {a0.x, a0.y, a0.z, a0.w,
                                  a1.x, a1.y, a1.z, a1.w};
            const float bv[16] = {b0.x, b0.y, b0.z, b0.w,
                                  b1.x, b1.y, b1.z, b1.w,
                                  b2.x, b2.y, b2.z, b2.w,
                                  b3.x, b3.y, b3.z, b3.w};
            #pragma unroll
            for (int i = 0; i < PX; ++i)
                #pragma unroll
                for (int jo = 0; jo < 4; ++jo)
                    acco[i][jo] = fmaf(a[i], bv[i + 2 * jo + 1], acco[i][jo]);
        }
        __syncthreads();
        buf ^= 1;
    }

    // ---- epilogue: mean over C, float4-pair stores ----
    const float scale = 1.0f / (float)CHN;
    const int y = y0 + yy;
    const int x = xt + 8 * xg;
    #pragma unroll
    for (int j = 0; j < NDISP; ++j) {
        const int d = w * NDISP + j;
        float* orow = &out[(((size_t)b * 81 + d) * HH + y) * WW + x];
        float p[PX];
        if ((j & 1) == 0) {
            #pragma unroll
            for (int i2 = 0; i2 < 4; ++i2)
                unpack2(p[2 * i2], p[2 * i2 + 1], acc2[i2][j >> 1]);
        } else {
            #pragma unroll
            for (int i = 0; i < PX; ++i)
                p[i] = acco[i][(j - 1) >> 1];
        }
        float4 o0, o1;
        o0.x = p[0] * scale; o0.y = p[1] * scale;
        o0.z = p[2] * scale; o0.w = p[3] * scale;
        o1.x = p[4] * scale; o1.y = p[5] * scale;
        o1.z = p[6] * scale; o1.w = p[7] * scale;
        *reinterpret_cast<float4*>(orow)     = o0;
        *reinterpret_cast<float4*>(orow + 4) = o1;
    }
}

extern "C" void kernel_launch(void* const* d_in, const int* in_sizes, int n_in,
                              void* d_out, int out_size)
{
    const float* first  = (const float*)d_in[0];
    const float* second = (const float*)d_in[1];
    float* out          = (float*)d_out;

    // Idempotent, deterministic, not stream-ordered (capture-safe).
    cudaFuncSetAttribute(corr_kernel,
                         cudaFuncAttributePreferredSharedMemoryCarveout, 100);

    dim3 grid(WW / TX, HH / TY, BATCH);   // (5, 24, 8)
    dim3 block(NTHREADS);
    corr_kernel<<<grid, block>>>(first, second, out);
}

// round 10
// speedup vs baseline: 1.9121x; 1.9121x over previous
#include <cuda_runtime.h>
#include <cstdint>

// Correlation layer: out[b, (dy+4)*9+(dx+4), y, x] =
//   (1/C) * sum_c first[b,c,y,x] * second[b,c,y+dy,x+dx]   (zero-padded)
// B=8, C=256, H=96, W=160, MAX_DISP=4 -> 81 displacements.
//
// R10 = R7 tiling (8-px strips, 2 dy/warp broadcast, padded strides 44/36)
//       + 3-stage cp.async ring: ONE __syncthreads per channel chunk,
//       staging always 2 chunks ahead of compute.

#define MAXD    4
#define NDISP   9
#define BATCH   8
#define CHN     256
#define HH      96
#define WW      160
#define HW      (HH*WW)

#define TY      4
#define TX      32
#define PX      8
#define CH      8
#define NITER   (CHN/CH)       // 32
#define NSTAGE  3

#define BROWS   (TY + 2*MAXD)  // 12
#define BCOLS   40
#define BSTR    44             // padded B row stride (floats)
#define ASTR    36             // padded A row stride (floats)
#define BTILEP  (BROWS*BSTR)   // 528
#define ATILEP  (TY*ASTR)      // 144
#define BUF_FLOATS (CH*(BTILEP+ATILEP))   // 5376 floats (21504 B)
#define BUF_BYTES  (BUF_FLOATS*4)
#define SMEM_BYTES (NSTAGE*BUF_BYTES)     // 64512 B

#define NTHREADS 144           // 4 xg * 4 yy * 9 w

#define NB4     (CH*BROWS*(BCOLS/4))   // 960
#define NA4     (CH*TY*(TX/4))         // 256
#define NTOT4   (NB4+NA4)              // 1216
#define NSLOT   9                      // ceil(1216/144)

__device__ __forceinline__ uint32_t smem_u32(const void* p) {
    return (uint32_t)__cvta_generic_to_shared(p);
}
__device__ __forceinline__ void cp16(uint32_t s, const void* g, int srcsz) {
    asm volatile("cp.async.cg.shared.global [%0], [%1], 16, %2;\n"
                 :: "r"(s), "l"(g), "r"(srcsz));
}
__device__ __forceinline__ void cp_commit() {
    asm volatile("cp.async.commit_group;\n" ::: "memory");
}
template<int N>
__device__ __forceinline__ void cp_wait() {
    asm volatile("cp.async.wait_group %0;\n" :: "n"(N) : "memory");
}

extern __shared__ float smem[];   // NSTAGE * BUF_FLOATS

__global__ __launch_bounds__(NTHREADS, 3)
void corr_kernel(const float* __restrict__ first,
                 const float* __restrict__ second,
                 float* __restrict__ out)
{
    const int xt  = blockIdx.x * TX;
    const int y0  = blockIdx.y * TY;
    const int b   = blockIdx.z;
    const int tid = threadIdx.x;

    // ---- precompute staging slots (hoisted out of channel loop) ----
    const float* gsrc[NSLOT];
    int          gsz [NSLOT];     // 16 = copy, 0 = zero-fill, -1 = skip
    uint32_t     sdst[NSLOT];     // byte address within buffer 0

    const size_t base = (size_t)b * CHN * HW;
    const uint32_t smem0 = smem_u32(smem);

    #pragma unroll
    for (int k = 0; k < NSLOT; ++k) {
        const int s = tid + k * NTHREADS;
        gsz[k]  = -1;
        gsrc[k] = first;
        sdst[k] = smem0;
        if (s < NB4) {
            // B halo: CH channels of 12 rows x 10 float4 (data cols 0..39)
            const int c   = s / 120;
            const int rem = s - c * 120;
            const int r   = rem / 10;
            const int q   = rem - r * 10;
            const int gy  = y0 - MAXD + r;
            const int gx  = xt - MAXD + 4 * q;
            const bool ok = ((unsigned)gy < (unsigned)HH) && (gx >= 0) && (gx + 4 <= WW);
            gsz[k]  = ok ? 16 : 0;
            gsrc[k] = ok ? (second + base + ((size_t)c * HH + gy) * WW + gx) : second;
            sdst[k] = smem0 + (uint32_t)(c * BTILEP + r * BSTR + 4 * q) * 4u;
        } else if (s < NTOT4) {
            // A tile: CH channels of 4 rows x 8 float4 (always in-bounds)
            const int j   = s - NB4;
            const int c   = j >> 5;
            const int rem = j & 31;
            const int r   = rem >> 3;
            const int q   = rem & 7;
            gsz[k]  = 16;
            gsrc[k] = first + base + ((size_t)c * HH + y0 + r) * WW + xt + 4 * q;
            sdst[k] = smem0 + (uint32_t)(CH * BTILEP + c * ATILEP + r * ASTR + 4 * q) * 4u;
        }
    }

    const int xg = tid & 3;           // x-group: pixels xt + 8*xg .. +7
    const int yy = (tid >> 2) & 3;    // row within tile
    const int w  = tid >> 4;          // dy index 0..8 (two per warp)

    float acc[PX][NDISP];             // 72 accumulators
    #pragma unroll
    for (int i = 0; i < PX; ++i)
        #pragma unroll
        for (int j = 0; j < NDISP; ++j)
            acc[i][j] = 0.0f;

    // ---- prologue: stage chunks 0 and 1 ----
    #pragma unroll
    for (int k = 0; k < NSLOT; ++k)
        if (gsz[k] >= 0) {
            cp16(sdst[k], gsrc[k], gsz[k]);
            gsrc[k] += CH * HW;
        }
    cp_commit();
    #pragma unroll
    for (int k = 0; k < NSLOT; ++k)
        if (gsz[k] >= 0) {
            cp16(sdst[k] + BUF_BYTES, gsrc[k], gsz[k]);
            gsrc[k] += CH * HW;
        }
    cp_commit();

    int cbuf = 0;                     // compute buffer index (it % 3)
    int sbuf = 2;                     // stage target index ((it+2) % 3)
    #pragma unroll 1
    for (int it = 0; it < NITER; ++it) {
        cp_wait<1>();                 // stage(it) landed (stage(it+1) may fly)
        __syncthreads();              // ...visible block-wide; compute(it-1) done

        // stage chunk it+2 into buffer (it+2)%3 (overwrites compute(it-1) buffer)
        if (it + 2 < NITER) {
            const uint32_t soff = (uint32_t)(sbuf * BUF_BYTES);
            #pragma unroll
            for (int k = 0; k < NSLOT; ++k)
                if (gsz[k] >= 0) {
                    cp16(sdst[k] + soff, gsrc[k], gsz[k]);
                    gsrc[k] += CH * HW;
                }
        }
        cp_commit();                  // (empty groups are fine for the tail)

        const float* Bb = smem + cbuf * BUF_FLOATS;
        const float* Ab = Bb + CH * BTILEP;
        #pragma unroll
        for (int cc = 0; cc < CH; ++cc) {
            const float* arow = &Ab[cc * ATILEP + yy * ASTR + 8 * xg];
            const float4 a0 = *reinterpret_cast<const float4*>(arow);
            const float4 a1 = *reinterpret_cast<const float4*>(arow + 4);

            // Pixel p = 8*xg+i uses halo cols 8*xg .. 8*xg+15
            const float* brow = &Bb[cc * BTILEP + (yy + w) * BSTR + 8 * xg];
            const float4 b0 = *reinterpret_cast<const float4*>(brow);
            const float4 b1 = *reinterpret_cast<const float4*>(brow + 4);
            const float4 b2 = *reinterpret_cast<const float4*>(brow + 8);
            const float4 b3 = *reinterpret_cast<const float4*>(brow + 12);

            const float a[PX]  = {a0.x, a0.y, a0.z, a0.w,
                                  a1.x, a1.y, a1.z, a1.w};
            const float bv[16] = {b0.x, b0.y, b0.z, b0.w,
                                  b1.x, b1.y, b1.z, b1.w,
                                  b2.x, b2.y, b2.z, b2.w,
                                  b3.x, b3.y, b3.z, b3.w};
            #pragma unroll
            for (int i = 0; i < PX; ++i)
                #pragma unroll
                for (int j = 0; j < NDISP; ++j)
                    acc[i][j] = fmaf(a[i], bv[i + j], acc[i][j]);
        }

        cbuf = (cbuf == NSTAGE - 1) ? 0 : cbuf + 1;
        sbuf = (sbuf == NSTAGE - 1) ? 0 : sbuf + 1;
    }

    // ---- epilogue: mean over C, float4-pair stores ----
    const float scale = 1.0f / (float)CHN;
    const int y = y0 + yy;
    const int x = xt + 8 * xg;
    #pragma unroll
    for (int j = 0; j < NDISP; ++j) {
        const int d = w * NDISP + j;
        float* orow = &out[(((size_t)b * 81 + d) * HH + y) * WW + x];
        float4 o0, o1;
        o0.x = acc[0][j] * scale; o0.y = acc[1][j] * scale;
        o0.z = acc[2][j] * scale; o0.w = acc[3][j] * scale;
        o1.x = acc[4][j] * scale; o1.y = acc[5][j] * scale;
        o1.z = acc[6][j] * scale; o1.w = acc[7][j] * scale;
        *reinterpret_cast<float4*>(orow)     = o0;
        *reinterpret_cast<float4*>(orow + 4) = o1;
    }
}

extern "C" void kernel_launch(void* const* d_in, const int* in_sizes, int n_in,
                              void* d_out, int out_size)
{
    const float* first  = (const float*)d_in[0];
    const float* second = (const float*)d_in[1];
    float* out          = (float*)d_out;

    // Idempotent, deterministic, not stream-ordered (capture-safe).
    cudaFuncSetAttribute(corr_kernel,
                         cudaFuncAttributeMaxDynamicSharedMemorySize, SMEM_BYTES);
    cudaFuncSetAttribute(corr_kernel,
                         cudaFuncAttributePreferredSharedMemoryCarveout, 100);

    dim3 grid(WW / TX, HH / TY, BATCH);   // (5, 24, 8)
    dim3 block(NTHREADS);
    corr_kernel<<<grid, block, SMEM_BYTES>>>(first, second, out);
}

// round 11
// speedup vs baseline: 1.9144x; 1.0012x over previous
#include <cuda_runtime.h>
#include <cstdint>

// Correlation layer: out[b, (dy+4)*9+(dx+4), y, x] =
//   (1/C) * sum_c first[b,c,y,x] * second[b,c,y+dy,x+dx]   (zero-padded)
// B=8, C=256, H=96, W=160, MAX_DISP=4 -> 81 displacements.
//
// R10 = R7 tiling (8-px strips, 2 dy/warp broadcast, padded strides 44/36)
//       + 3-stage cp.async ring: ONE __syncthreads per channel chunk,
//       staging always 2 chunks ahead of compute.

#define MAXD    4
#define NDISP   9
#define BATCH   8
#define CHN     256
#define HH      96
#define WW      160
#define HW      (HH*WW)

#define TY      4
#define TX      32
#define PX      8
#define CH      8
#define NITER   (CHN/CH)       // 32
#define NSTAGE  3

#define BROWS   (TY + 2*MAXD)  // 12
#define BCOLS   40
#define BSTR    44             // padded B row stride (floats)
#define ASTR    36             // padded A row stride (floats)
#define BTILEP  (BROWS*BSTR)   // 528
#define ATILEP  (TY*ASTR)      // 144
#define BUF_FLOATS (CH*(BTILEP+ATILEP))   // 5376 floats (21504 B)
#define BUF_BYTES  (BUF_FLOATS*4)
#define SMEM_BYTES (NSTAGE*BUF_BYTES)     // 64512 B

#define NTHREADS 144           // 4 xg * 4 yy * 9 w

#define NB4     (CH*BROWS*(BCOLS/4))   // 960
#define NA4     (CH*TY*(TX/4))         // 256
#define NTOT4   (NB4+NA4)              // 1216
#define NSLOT   9                      // ceil(1216/144)

__device__ __forceinline__ uint32_t smem_u32(const void* p) {
    return (uint32_t)__cvta_generic_to_shared(p);
}
__device__ __forceinline__ void cp16(uint32_t s, const void* g, int srcsz) {
    asm volatile("cp.async.cg.shared.global [%0], [%1], 16, %2;\n"
                 :: "r"(s), "l"(g), "r"(srcsz));
}
__device__ __forceinline__ void cp_commit() {
    asm volatile("cp.async.commit_group;\n" ::: "memory");
}
template<int N>
__device__ __forceinline__ void cp_wait() {
    asm volatile("cp.async.wait_group %0;\n" :: "n"(N) : "memory");
}

extern __shared__ float smem[];   // NSTAGE * BUF_FLOATS

__global__ __launch_bounds__(NTHREADS, 3)
void corr_kernel(const float* __restrict__ first,
                 const float* __restrict__ second,
                 float* __restrict__ out)
{
    const int xt  = blockIdx.x * TX;
    const int y0  = blockIdx.y * TY;
    const int b   = blockIdx.z;
    const int tid = threadIdx.x;

    // ---- precompute staging slots (hoisted out of channel loop) ----
    const float* gsrc[NSLOT];
    int          gsz [NSLOT];     // 16 = copy, 0 = zero-fill, -1 = skip
    uint32_t     sdst[NSLOT];     // byte address within buffer 0

    const size_t base = (size_t)b * CHN * HW;
    const uint32_t smem0 = smem_u32(smem);

    #pragma unroll
    for (int k = 0; k < NSLOT; ++k) {
        const int s = tid + k * NTHREADS;
        gsz[k]  = -1;
        gsrc[k] = first;
        sdst[k] = smem0;
        if (s < NB4) {
            // B halo: CH channels of 12 rows x 10 float4 (data cols 0..39)
            const int c   = s / 120;
            const int rem = s - c * 120;
            const int r   = rem / 10;
            const int q   = rem - r * 10;
            const int gy  = y0 - MAXD + r;
            const int gx  = xt - MAXD + 4 * q;
            const bool ok = ((unsigned)gy < (unsigned)HH) && (gx >= 0) && (gx + 4 <= WW);
            gsz[k]  = ok ? 16 : 0;
            gsrc[k] = ok ? (second + base + ((size_t)c * HH + gy) * WW + gx) : second;
            sdst[k] = smem0 + (uint32_t)(c * BTILEP + r * BSTR + 4 * q) * 4u;
        } else if (s < NTOT4) {
            // A tile: CH channels of 4 rows x 8 float4 (always in-bounds)
            const int j   = s - NB4;
            const int c   = j >> 5;
            const int rem = j & 31;
            const int r   = rem >> 3;
            const int q   = rem & 7;
            gsz[k]  = 16;
            gsrc[k] = first + base + ((size_t)c * HH + y0 + r) * WW + xt + 4 * q;
            sdst[k] = smem0 + (uint32_t)(CH * BTILEP + c * ATILEP + r * ASTR + 4 * q) * 4u;
        }
    }

    const int xg = tid & 3;           // x-group: pixels xt + 8*xg .. +7
    const int yy = (tid >> 2) & 3;    // row within tile
    const int w  = tid >> 4;          // dy index 0..8 (two per warp)

    float acc[PX][NDISP];             // 72 accumulators
    #pragma unroll
    for (int i = 0; i < PX; ++i)
        #pragma unroll
        for (int j = 0; j < NDISP; ++j)
            acc[i][j] = 0.0f;

    // ---- prologue: stage chunks 0 and 1 ----
    #pragma unroll
    for (int k = 0; k < NSLOT; ++k)
        if (gsz[k] >= 0) {
            cp16(sdst[k], gsrc[k], gsz[k]);
            gsrc[k] += CH * HW;
        }
    cp_commit();
    #pragma unroll
    for (int k = 0; k < NSLOT; ++k)
        if (gsz[k] >= 0) {
            cp16(sdst[k] + BUF_BYTES, gsrc[k], gsz[k]);
            gsrc[k] += CH * HW;
        }
    cp_commit();

    int cbuf = 0;                     // compute buffer index (it % 3)
    int sbuf = 2;                     // stage target index ((it+2) % 3)
    #pragma unroll 1
    for (int it = 0; it < NITER; ++it) {
        cp_wait<1>();                 // stage(it) landed (stage(it+1) may fly)
        __syncthreads();              // ...visible block-wide; compute(it-1) done

        // stage chunk it+2 into buffer (it+2)%3 (overwrites compute(it-1) buffer)
        if (it + 2 < NITER) {
            const uint32_t soff = (uint32_t)(sbuf * BUF_BYTES);
            #pragma unroll
            for (int k = 0; k < NSLOT; ++k)
                if (gsz[k] >= 0) {
                    cp16(sdst[k] + soff, gsrc[k], gsz[k]);
                    gsrc[k] += CH * HW;
                }
        }
        cp_commit();                  // (empty groups are fine for the tail)

        const float* Bb = smem + cbuf * BUF_FLOATS;
        const float* Ab = Bb + CH * BTILEP;
        #pragma unroll
        for (int cc = 0; cc < CH; ++cc) {
            const float* arow = &Ab[cc * ATILEP + yy * ASTR + 8 * xg];
            const float4 a0 = *reinterpret_cast<const float4*>(arow);
            const float4 a1 = *reinterpret_cast<const float4*>(arow + 4);

            // Pixel p = 8*xg+i uses halo cols 8*xg .. 8*xg+15
            const float* brow = &Bb[cc * BTILEP + (yy + w) * BSTR + 8 * xg];
            const float4 b0 = *reinterpret_cast<const float4*>(brow);
            const float4 b1 = *reinterpret_cast<const float4*>(brow + 4);
            const float4 b2 = *reinterpret_cast<const float4*>(brow + 8);
            const float4 b3 = *reinterpret_cast<const float4*>(brow + 12);

            const float a[PX]  = {a0.x, a0.y, a0.z, a0.w,
                                  a1.x, a1.y, a1.z, a1.w};
            const float bv[16] = {b0.x, b0.y, b0.z, b0.w,
                                  b1.x, b1.y, b1.z, b1.w,
                                  b2.x, b2.y, b2.z, b2.w,
                                  b3.x, b3.y, b3.z, b3.w};
            #pragma unroll
            for (int i = 0; i < PX; ++i)
                #pragma unroll
                for (int j = 0; j < NDISP; ++j)
                    acc[i][j] = fmaf(a[i], bv[i + j], acc[i][j]);
        }

        cbuf = (cbuf == NSTAGE - 1) ? 0 : cbuf + 1;
        sbuf = (sbuf == NSTAGE - 1) ? 0 : sbuf + 1;
    }

    // ---- epilogue: mean over C, float4-pair stores ----
    const float scale = 1.0f / (float)CHN;
    const int y = y0 + yy;
    const int x = xt + 8 * xg;
    #pragma unroll
    for (int j = 0; j < NDISP; ++j) {
        const int d = w * NDISP + j;
        float* orow = &out[(((size_t)b * 81 + d) * HH + y) * WW + x];
        float4 o0, o1;
        o0.x = acc[0][j] * scale; o0.y = acc[1][j] * scale;
        o0.z = acc[2][j] * scale; o0.w = acc[3][j] * scale;
        o1.x = acc[4][j] * scale; o1.y = acc[5][j] * scale;
        o1.z = acc[6][j] * scale; o1.w = acc[7][j] * scale;
        *reinterpret_cast<float4*>(orow)     = o0;
        *reinterpret_cast<float4*>(orow + 4) = o1;
    }
}

extern "C" void kernel_launch(void* const* d_in, const int* in_sizes, int n_in,
                              void* d_out, int out_size)
{
    const float* first  = (const float*)d_in[0];
    const float* second = (const float*)d_in[1];
    float* out          = (float*)d_out;

    // Idempotent, deterministic, not stream-ordered (capture-safe).
    cudaFuncSetAttribute(corr_kernel,
                         cudaFuncAttributeMaxDynamicSharedMemorySize, SMEM_BYTES);
    cudaFuncSetAttribute(corr_kernel,
                         cudaFuncAttributePreferredSharedMemoryCarveout, 100);

    dim3 grid(WW / TX, HH / TY, BATCH);   // (5, 24, 8)
    dim3 block(NTHREADS);
    corr_kernel<<<grid, block, SMEM_BYTES>>>(first, second, out);
}